// round 2
// baseline (speedup 1.0000x reference)
#include <cuda_runtime.h>
#include <cuda_fp16.h>
#include <cstdint>

// ---------------- problem sizes ----------------
#define BB   16
#define CI   512
#define CO   512
#define HW_  64
#define DL   512
#define HPAD 66

#define C_LIN  0.044194173824159216f   // 1/sqrt(512)
#define C_CONV 0.014731391274719739f   // 1/sqrt(512*9)

// ---------------- device scratch (no runtime alloc allowed) ----------------
__device__ __half g_wh[9 * CO * CI];                   // weights fp16, tap-major [9][CO][CI]
__device__ float  g_wsq[CO * CI];                      // sum_k conv_w^2
__device__ float  g_z0[BB * DL];
__device__ float  g_z1[BB * DL];
__device__ float  g_style[BB * CI];
__device__ float  g_sout[BB * CO];                     // c_conv * sigma_inv
__device__ __half g_xp[(size_t)BB * HPAD * HPAD * CI]; // NHWC padded modulated input

// ---------------- helpers ----------------
__device__ __forceinline__ uint32_t smem_u32(const void* p) {
    uint32_t a;
    asm("{ .reg .u64 t; cvta.to.shared.u64 t, %1; cvt.u32.u64 %0, t; }" : "=r"(a) : "l"(p));
    return a;
}

__device__ __forceinline__ uint32_t swz(uint32_t x) { return x ^ ((x >> 3) & 0x70); }

#define CP16(smem, gptr) \
    asm volatile("cp.async.cg.shared.global [%0], [%1], 16;" :: "r"(smem), "l"(gptr))
#define CP_COMMIT() asm volatile("cp.async.commit_group;" ::: "memory")
#define CP_WAIT(n)  asm volatile("cp.async.wait_group %0;" :: "n"(n) : "memory")

__device__ __forceinline__ void ldsm_x4(uint32_t& r0, uint32_t& r1, uint32_t& r2, uint32_t& r3,
                                        uint32_t addr) {
    asm volatile("ldmatrix.sync.aligned.m8n8.x4.shared.b16 {%0,%1,%2,%3}, [%4];"
                 : "=r"(r0), "=r"(r1), "=r"(r2), "=r"(r3) : "r"(addr));
}

__device__ __forceinline__ void mma16816(float* c, const uint32_t* a, uint32_t b0, uint32_t b1) {
    asm volatile(
        "mma.sync.aligned.m16n8k16.row.col.f32.f16.f16.f32 "
        "{%0,%1,%2,%3}, {%4,%5,%6,%7}, {%8,%9}, {%0,%1,%2,%3};"
        : "+f"(c[0]), "+f"(c[1]), "+f"(c[2]), "+f"(c[3])
        : "r"(a[0]), "r"(a[1]), "r"(a[2]), "r"(a[3]), "r"(b0), "r"(b1));
}

// ---------------- kernel 0: weight prep ----------------
__global__ void prep_weights(const float* __restrict__ cw) {
    int g = blockIdx.x * blockDim.x + threadIdx.x;   // g = o*512 + i
    const float* p = cw + (size_t)g * 9;
    float sq = 0.f;
#pragma unroll
    for (int k = 0; k < 9; k++) {
        float v = p[k];
        sq = fmaf(v, v, sq);
        g_wh[(size_t)k * (CO * CI) + g] = __float2half(v);
    }
    g_wsq[g] = sq;
}

// ---------------- kernel 1: mapping network layers ----------------
__global__ void linear_map(const float* __restrict__ ext_in, const float* __restrict__ W,
                           const float* __restrict__ bias, const float* __restrict__ pa,
                           int mode) {
    __shared__ float sin_t[DL * BB];  // transposed [j][b]
    const float* in = (mode == 0) ? ext_in : (mode == 1 ? g_z0 : g_z1);
    float* out      = (mode == 0) ? g_z0   : (mode == 1 ? g_z1 : g_style);
    int tid = threadIdx.x;  // 512
    for (int idx = tid; idx < BB * DL; idx += 512) {
        int b = idx >> 9, j = idx & 511;
        sin_t[j * BB + b] = in[idx];
    }
    __syncthreads();
    int b = tid & 15;
    int o = blockIdx.x * 32 + (tid >> 4);
    const float* wr = W + (size_t)o * DL;
    float acc = 0.f;
#pragma unroll 4
    for (int j = 0; j < DL; j++)
        acc = fmaf(sin_t[j * BB + b], wr[j], acc);
    float r = acc * C_LIN + bias[o];
    if (mode < 2) r = (r >= 0.f) ? r : pa[o] * r;
    out[b * DL + o] = r;
}

// ---------------- kernel 2: output scale ----------------
__global__ void sigma_kernel() {
    __shared__ float st2[CI * BB];
    int tid = threadIdx.x;
    for (int idx = tid; idx < BB * CI; idx += 512) {
        int b = idx >> 9, j = idx & 511;
        float v = g_style[idx];
        st2[j * BB + b] = v * v;
    }
    __syncthreads();
    int b = tid & 15;
    int o = blockIdx.x * 32 + (tid >> 4);
    const float* wr = g_wsq + (size_t)o * CI;
    float acc = 0.f;
#pragma unroll 4
    for (int j = 0; j < CI; j++)
        acc = fmaf(st2[j * BB + b], wr[j], acc);
    g_sout[b * CO + o] = C_CONV * rsqrtf(C_CONV * C_CONV * acc + 1e-8f);
}

// ---------------- kernel 3: modulate + edge-pad + NCHW->NHWC fp16 ----------------
__global__ void mod_pad(const float* __restrict__ x) {
    __shared__ float sx[64][65];
    __shared__ float sst[64];
    int i0 = blockIdx.x * 64;
    int hp = blockIdx.y;
    int b  = blockIdx.z;
    int h = hp - 1; h = h < 0 ? 0 : (h > 63 ? 63 : h);
    int tid = threadIdx.x;
    const float* xb = x + (((size_t)b * CI + i0) * 64 + h) * 64;
    for (int idx = tid; idx < 64 * 16; idx += 256) {
        int i = idx >> 4, w4 = (idx & 15) << 2;
        float4 v = *(const float4*)(xb + (size_t)i * 4096 + w4);
        sx[i][w4] = v.x; sx[i][w4 + 1] = v.y; sx[i][w4 + 2] = v.z; sx[i][w4 + 3] = v.w;
    }
    if (tid < 64) sst[tid] = g_style[b * CI + i0 + tid];
    __syncthreads();
    __half* outp = g_xp + (((size_t)b * HPAD + hp) * HPAD) * CI + i0;
    for (int idx = tid; idx < 66 * 32; idx += 256) {
        int wp = idx >> 5; int ip = (idx & 31) << 1;
        int w = wp - 1; w = w < 0 ? 0 : (w > 63 ? 63 : w);
        __half2 hv = __floats2half2_rn(sx[ip][w] * sst[ip], sx[ip + 1][w] * sst[ip + 1]);
        *(__half2*)(outp + (size_t)wp * CI + ip) = hv;
    }
}

// ---------------- kernel 4: conv as implicit GEMM (HMMA, cp.async 3-stage) ----------------
// CTA tile: M=128 (cout) x N=128 (pixels = 2 image rows). K = 72 chunks of 64.
// 8 warps (4 in M x 2 in N), warp tile 32x64, mma.m16n8k16 fp16->fp32.
#define STAGE_BYTES 32768u   // A 16KB + B 16KB
#define NSTAGE 3
#define SMEM_BYTES (NSTAGE * STAGE_BYTES)
#define NCHUNK 72

__device__ __forceinline__ void load_chunk_async(int tid, uint32_t sbase, int stage, int j,
                                                 int o0, int h0, const __half* __restrict__ xpb) {
    uint32_t sA = sbase + (uint32_t)stage * STAGE_BYTES;
    uint32_t sB = sA + 16384u;
    int tap = j >> 3, cc = j & 7;
    int dh = tap / 3, dw = tap - dh * 3;
    int r   = tid >> 3;       // 0..31
    int col = tid & 7;        // 16B column
    uint32_t cbyte = (uint32_t)col << 4;
    const __half* ab = g_wh + (((size_t)((tap << 9) + o0)) << 9) + (cc << 6) + (col << 3);
#pragma unroll
    for (int k = 0; k < 4; k++) {        // A: 128 rows of cout
        int row = r + (k << 5);
        CP16(sA + swz(((uint32_t)row << 7) + cbyte), ab + ((size_t)row << 9));
    }
#pragma unroll
    for (int k = 0; k < 4; k++) {        // B: 128 pixel rows
        int row = r + (k << 5);
        int hp = h0 + (row >> 6) + dh;
        int wp = (row & 63) + dw;
        CP16(sB + swz(((uint32_t)row << 7) + cbyte),
             xpb + (((size_t)(hp * HPAD + wp)) << 9) + (cc << 6) + (col << 3));
    }
}

__global__ void __launch_bounds__(256, 1) conv_kernel(float* __restrict__ out) {
    extern __shared__ char smem[];
    const uint32_t sbase = smem_u32(smem);
    int tid  = threadIdx.x;
    int w    = tid >> 5;
    int lane = tid & 31;
    int m0w  = (w >> 1) << 5;   // warp M offset 0..96
    int n0w  = (w & 1) << 6;    // warp N offset 0/64

    int tile = blockIdx.x;
    int nt = tile & 31;
    int ot = (tile >> 5) & 3;
    int b  = tile >> 7;
    int o0 = ot << 7;
    int n0 = nt << 7;           // pixel offset
    int h0 = nt << 1;           // image row offset

    const __half* xpb = g_xp + (size_t)b * (HPAD * HPAD * CI);

    // prologue: stages 0,1
    load_chunk_async(tid, sbase, 0, 0, o0, h0, xpb);
    CP_COMMIT();
    load_chunk_async(tid, sbase, 1, 1, o0, h0, xpb);
    CP_COMMIT();

    float acc[2][8][4];
#pragma unroll
    for (int i = 0; i < 2; i++)
#pragma unroll
        for (int jn = 0; jn < 8; jn++)
#pragma unroll
            for (int c = 0; c < 4; c++) acc[i][jn][c] = 0.f;

    // ldmatrix lane address components
    uint32_t rowA = (uint32_t)(m0w + (lane & 15));              // + 16*mi
    uint32_t kselA = (uint32_t)((lane >> 4) << 4);              // byte offset 0/16
    uint32_t rowB = (uint32_t)(n0w + (lane & 7) + ((lane & 16) >> 1));  // + 16*jj
    uint32_t kselB = (uint32_t)((lane & 8) << 1);               // byte offset 0/16

    int stage = 0;
    for (int j = 0; j < NCHUNK; j++) {
        CP_WAIT(1);
        __syncthreads();

        // prefetch chunk j+2 into the free stage
        int js = j + 2;
        if (js < NCHUNK) {
            int st2 = js - (js / NSTAGE) * NSTAGE;
            load_chunk_async(tid, sbase, st2, js, o0, h0, xpb);
        }
        CP_COMMIT();

        uint32_t sA = sbase + (uint32_t)stage * STAGE_BYTES;
        uint32_t sB = sA + 16384u;
#pragma unroll
        for (int kk = 0; kk < 4; kk++) {
            uint32_t kb = (uint32_t)(kk << 5);   // k byte base (16 halves)
            uint32_t a[2][4];
#pragma unroll
            for (int mi = 0; mi < 2; mi++)
                ldsm_x4(a[mi][0], a[mi][1], a[mi][2], a[mi][3],
                        sA + swz(((rowA + (mi << 4)) << 7) + kb + kselA));
            uint32_t bf[4][4];
#pragma unroll
            for (int jj = 0; jj < 4; jj++)
                ldsm_x4(bf[jj][0], bf[jj][1], bf[jj][2], bf[jj][3],
                        sB + swz(((rowB + (jj << 4)) << 7) + kb + kselB));
#pragma unroll
            for (int mi = 0; mi < 2; mi++)
#pragma unroll
                for (int jn = 0; jn < 8; jn++)
                    mma16816(acc[mi][jn], a[mi], bf[jn >> 1][(jn & 1) << 1],
                             bf[jn >> 1][((jn & 1) << 1) + 1]);
        }
        stage++;
        if (stage == NSTAGE) stage = 0;
    }

    // epilogue: scale by sout[b][o], write fp32
    const float* svb = g_sout + (b << 9) + o0;
#pragma unroll
    for (int mi = 0; mi < 2; mi++) {
        int r0 = m0w + (mi << 4) + (lane >> 2);
        float sv0 = svb[r0];
        float sv1 = svb[r0 + 8];
        float* p0 = out + (((size_t)((b << 9) + o0 + r0)) << 12) + n0 + n0w;
        float* p1 = p0 + ((size_t)8 << 12);
#pragma unroll
        for (int jn = 0; jn < 8; jn++) {
            int c = (jn << 3) + ((lane & 3) << 1);
            float2 v0 = make_float2(acc[mi][jn][0] * sv0, acc[mi][jn][1] * sv0);
            float2 v1 = make_float2(acc[mi][jn][2] * sv1, acc[mi][jn][3] * sv1);
            *(float2*)(p0 + c) = v0;
            *(float2*)(p1 + c) = v1;
        }
    }
}

// ---------------- launch ----------------
extern "C" void kernel_launch(void* const* d_in, const int* in_sizes, int n_in,
                              void* d_out, int out_size) {
    (void)in_sizes; (void)n_in; (void)out_size;
    const float* x  = (const float*)d_in[0];
    const float* s  = (const float*)d_in[1];
    const float* w0 = (const float*)d_in[2];
    const float* b0 = (const float*)d_in[3];
    const float* a0 = (const float*)d_in[4];
    const float* w1 = (const float*)d_in[5];
    const float* b1 = (const float*)d_in[6];
    const float* a1 = (const float*)d_in[7];
    const float* sw = (const float*)d_in[8];
    const float* sb = (const float*)d_in[9];
    const float* cw = (const float*)d_in[10];
    float* out = (float*)d_out;

    cudaFuncSetAttribute(conv_kernel, cudaFuncAttributeMaxDynamicSharedMemorySize, SMEM_BYTES);

    prep_weights<<<(CO * CI) / 256, 256>>>(cw);
    linear_map<<<16, 512>>>(s, w0, b0, a0, 0);
    linear_map<<<16, 512>>>(nullptr, w1, b1, a1, 1);
    linear_map<<<16, 512>>>(nullptr, sw, sb, nullptr, 2);
    sigma_kernel<<<16, 512>>>();
    mod_pad<<<dim3(CI / 64, HPAD, BB), 256>>>(x);
    conv_kernel<<<BB * 4 * 32, 256, SMEM_BYTES>>>(out);
}

// round 3
// speedup vs baseline: 1.2186x; 1.2186x over previous
#include <cuda_runtime.h>
#include <cuda_fp16.h>
#include <cstdint>

// ---------------- problem sizes ----------------
#define BB   16
#define CI   512
#define CO   512
#define HW_  64
#define DL   512
#define HPAD 66

#define C_LIN  0.044194173824159216f   // 1/sqrt(512)
#define C_CONV 0.014731391274719739f   // 1/sqrt(512*9)

// ---------------- device scratch (no runtime alloc allowed) ----------------
__device__ __half g_wh[9 * CO * CI];                   // weights fp16, tap-major [9][CO][CI]
__device__ float  g_wsq[CO * CI];                      // sum_k conv_w^2
__device__ float  g_z0[BB * DL];
__device__ float  g_z1[BB * DL];
__device__ float  g_style[BB * CI];
__device__ float  g_sout[BB * CO];                     // c_conv * sigma_inv
__device__ __half g_xp[(size_t)BB * HPAD * HPAD * CI]; // NHWC padded modulated input

// ---------------- helpers ----------------
__device__ __forceinline__ uint32_t smem_u32(const void* p) {
    uint32_t a;
    asm("{ .reg .u64 t; cvta.to.shared.u64 t, %1; cvt.u32.u64 %0, t; }" : "=r"(a) : "l"(p));
    return a;
}

__device__ __forceinline__ uint32_t swz(uint32_t x) { return x ^ ((x >> 3) & 0x70); }

#define CP16(smem, gptr) \
    asm volatile("cp.async.cg.shared.global [%0], [%1], 16;" :: "r"(smem), "l"(gptr))
#define CP_COMMIT() asm volatile("cp.async.commit_group;" ::: "memory")
#define CP_WAIT(n)  asm volatile("cp.async.wait_group %0;" :: "n"(n) : "memory")

__device__ __forceinline__ void ldsm_x4(uint32_t& r0, uint32_t& r1, uint32_t& r2, uint32_t& r3,
                                        uint32_t addr) {
    asm volatile("ldmatrix.sync.aligned.m8n8.x4.shared.b16 {%0,%1,%2,%3}, [%4];"
                 : "=r"(r0), "=r"(r1), "=r"(r2), "=r"(r3) : "r"(addr));
}

__device__ __forceinline__ void mma16816(float* c, const uint32_t* a, uint32_t b0, uint32_t b1) {
    asm volatile(
        "mma.sync.aligned.m16n8k16.row.col.f32.f16.f16.f32 "
        "{%0,%1,%2,%3}, {%4,%5,%6,%7}, {%8,%9}, {%0,%1,%2,%3};"
        : "+f"(c[0]), "+f"(c[1]), "+f"(c[2]), "+f"(c[3])
        : "r"(a[0]), "r"(a[1]), "r"(a[2]), "r"(a[3]), "r"(b0), "r"(b1));
}

// ---------------- kernel 0: weight prep ----------------
__global__ void prep_weights(const float* __restrict__ cw) {
    int g = blockIdx.x * blockDim.x + threadIdx.x;   // g = o*512 + i
    const float* p = cw + (size_t)g * 9;
    float sq = 0.f;
#pragma unroll
    for (int k = 0; k < 9; k++) {
        float v = p[k];
        sq = fmaf(v, v, sq);
        g_wh[(size_t)k * (CO * CI) + g] = __float2half(v);
    }
    g_wsq[g] = sq;
}

// ---------------- kernel 1: mapping network layers (high-MLP GEMV) ----------------
__global__ void linear_map(const float* __restrict__ ext_in, const float* __restrict__ W,
                           const float* __restrict__ bias, const float* __restrict__ pa,
                           int mode) {
    __shared__ float sin_t[DL * BB];  // transposed [j][b]
    const float* in = (mode == 0) ? ext_in : (mode == 1 ? g_z0 : g_z1);
    float* out      = (mode == 0) ? g_z0   : (mode == 1 ? g_z1 : g_style);
    int tid = threadIdx.x;  // 512
    for (int idx = tid; idx < BB * DL; idx += 512) {
        int b = idx >> 9, j = idx & 511;
        sin_t[j * BB + b] = in[idx];
    }
    __syncthreads();
    int b = tid & 15;
    int o = blockIdx.x * 32 + (tid >> 4);
    const float4* wr = (const float4*)(W + (size_t)o * DL);
    float a0 = 0.f, a1 = 0.f, a2 = 0.f, a3 = 0.f;
#pragma unroll 16
    for (int j4 = 0; j4 < DL / 4; j4++) {
        float4 wv = __ldg(wr + j4);
        int j = j4 << 2;
        a0 = fmaf(sin_t[(j + 0) * BB + b], wv.x, a0);
        a1 = fmaf(sin_t[(j + 1) * BB + b], wv.y, a1);
        a2 = fmaf(sin_t[(j + 2) * BB + b], wv.z, a2);
        a3 = fmaf(sin_t[(j + 3) * BB + b], wv.w, a3);
    }
    float r = ((a0 + a1) + (a2 + a3)) * C_LIN + bias[o];
    if (mode < 2) r = (r >= 0.f) ? r : pa[o] * r;
    out[b * DL + o] = r;
}

// ---------------- kernel 2: output scale ----------------
__global__ void sigma_kernel() {
    __shared__ float st2[CI * BB];
    int tid = threadIdx.x;
    for (int idx = tid; idx < BB * CI; idx += 512) {
        int b = idx >> 9, j = idx & 511;
        float v = g_style[idx];
        st2[j * BB + b] = v * v;
    }
    __syncthreads();
    int b = tid & 15;
    int o = blockIdx.x * 32 + (tid >> 4);
    const float4* wr = (const float4*)(g_wsq + (size_t)o * CI);
    float a0 = 0.f, a1 = 0.f, a2 = 0.f, a3 = 0.f;
#pragma unroll 16
    for (int j4 = 0; j4 < CI / 4; j4++) {
        float4 wv = __ldg(wr + j4);
        int j = j4 << 2;
        a0 = fmaf(st2[(j + 0) * BB + b], wv.x, a0);
        a1 = fmaf(st2[(j + 1) * BB + b], wv.y, a1);
        a2 = fmaf(st2[(j + 2) * BB + b], wv.z, a2);
        a3 = fmaf(st2[(j + 3) * BB + b], wv.w, a3);
    }
    float acc = (a0 + a1) + (a2 + a3);
    g_sout[b * CO + o] = C_CONV * rsqrtf(C_CONV * C_CONV * acc + 1e-8f);
}

// ---------------- kernel 3: modulate + edge-pad + NCHW->NHWC fp16 ----------------
__global__ void mod_pad(const float* __restrict__ x) {
    __shared__ float sx[64][65];
    __shared__ float sst[64];
    int i0 = blockIdx.x * 64;
    int hp = blockIdx.y;
    int b  = blockIdx.z;
    int h = hp - 1; h = h < 0 ? 0 : (h > 63 ? 63 : h);
    int tid = threadIdx.x;
    const float* xb = x + (((size_t)b * CI + i0) * 64 + h) * 64;
    for (int idx = tid; idx < 64 * 16; idx += 256) {
        int i = idx >> 4, w4 = (idx & 15) << 2;
        float4 v = *(const float4*)(xb + (size_t)i * 4096 + w4);
        sx[i][w4] = v.x; sx[i][w4 + 1] = v.y; sx[i][w4 + 2] = v.z; sx[i][w4 + 3] = v.w;
    }
    if (tid < 64) sst[tid] = g_style[b * CI + i0 + tid];
    __syncthreads();
    __half* outp = g_xp + (((size_t)b * HPAD + hp) * HPAD) * CI + i0;
    for (int idx = tid; idx < 66 * 32; idx += 256) {
        int wp = idx >> 5; int ip = (idx & 31) << 1;
        int w = wp - 1; w = w < 0 ? 0 : (w > 63 ? 63 : w);
        __half2 hv = __floats2half2_rn(sx[ip][w] * sst[ip], sx[ip + 1][w] * sst[ip + 1]);
        *(__half2*)(outp + (size_t)wp * CI + ip) = hv;
    }
}

// ---------------- kernel 4: conv as implicit GEMM (HMMA, cp.async 3-stage) ----------------
// CTA tile: M=128 (cout) x N=256 (pixels = 4 image rows). K = 72 chunks of 64.
// 8 warps (2 in M x 4 in N), warp tile 64x64, mma.m16n8k16 fp16->fp32.
#define STAGE_BYTES 49152u   // A 16KB + B 32KB
#define NSTAGE 3
#define SMEM_BYTES (NSTAGE * STAGE_BYTES)   // 147456
#define NCHUNK 72

__device__ __forceinline__ void load_chunk_async(int tid, uint32_t sbase, int stage, int j,
                                                 int o0, int h0, const __half* __restrict__ xpb) {
    uint32_t sA = sbase + (uint32_t)stage * STAGE_BYTES;
    uint32_t sB = sA + 16384u;
    int tap = j >> 3, cc = j & 7;
    int dh = tap / 3, dw = tap - dh * 3;
    int r   = tid >> 3;       // 0..31
    int col = tid & 7;        // 16B column
    uint32_t cbyte = (uint32_t)col << 4;
    const __half* ab = g_wh + (((size_t)((tap << 9) + o0)) << 9) + (cc << 6) + (col << 3);
#pragma unroll
    for (int k = 0; k < 4; k++) {        // A: 128 rows of cout
        int row = r + (k << 5);
        CP16(sA + swz(((uint32_t)row << 7) + cbyte), ab + ((size_t)row << 9));
    }
#pragma unroll
    for (int k = 0; k < 8; k++) {        // B: 256 pixel rows
        int row = r + (k << 5);
        int hp = h0 + (row >> 6) + dh;
        int wp = (row & 63) + dw;
        CP16(sB + swz(((uint32_t)row << 7) + cbyte),
             xpb + (((size_t)(hp * HPAD + wp)) << 9) + (cc << 6) + (col << 3));
    }
}

__global__ void __launch_bounds__(256, 1) conv_kernel(float* __restrict__ out) {
    extern __shared__ char smem[];
    const uint32_t sbase = smem_u32(smem);
    int tid  = threadIdx.x;
    int w    = tid >> 5;
    int lane = tid & 31;
    int m0w  = (w & 1) << 6;    // warp M offset 0/64
    int n0w  = (w >> 1) << 6;   // warp N offset 0..192

    int tile = blockIdx.x;
    int nt = tile & 15;
    int ot = (tile >> 4) & 3;
    int b  = tile >> 6;
    int o0 = ot << 7;
    int n0 = nt << 8;           // pixel offset
    int h0 = nt << 2;           // image row offset (4 rows per tile)

    const __half* xpb = g_xp + (size_t)b * (HPAD * HPAD * CI);

    // prologue: stages 0,1
    load_chunk_async(tid, sbase, 0, 0, o0, h0, xpb);
    CP_COMMIT();
    load_chunk_async(tid, sbase, 1, 1, o0, h0, xpb);
    CP_COMMIT();

    float acc[4][8][4];
#pragma unroll
    for (int i = 0; i < 4; i++)
#pragma unroll
        for (int jn = 0; jn < 8; jn++)
#pragma unroll
            for (int c = 0; c < 4; c++) acc[i][jn][c] = 0.f;

    // ldmatrix lane address components
    uint32_t rowA = (uint32_t)(m0w + (lane & 15));                      // + 16*mi
    uint32_t kselA = (uint32_t)((lane >> 4) << 4);                      // byte offset 0/16
    uint32_t rowB = (uint32_t)(n0w + (lane & 7) + ((lane & 16) >> 1));  // + 16*jj
    uint32_t kselB = (uint32_t)((lane & 8) << 1);                       // byte offset 0/16

    int stage = 0;
    for (int j = 0; j < NCHUNK; j++) {
        CP_WAIT(1);
        __syncthreads();

        // prefetch chunk j+2 into the free stage
        int js = j + 2;
        if (js < NCHUNK) {
            int st2 = js - (js / NSTAGE) * NSTAGE;
            load_chunk_async(tid, sbase, st2, js, o0, h0, xpb);
        }
        CP_COMMIT();

        uint32_t sA = sbase + (uint32_t)stage * STAGE_BYTES;
        uint32_t sB = sA + 16384u;
#pragma unroll
        for (int kk = 0; kk < 4; kk++) {
            uint32_t kb = (uint32_t)(kk << 5);   // k byte base (16 halves)
            uint32_t a[4][4];
#pragma unroll
            for (int mi = 0; mi < 4; mi++)
                ldsm_x4(a[mi][0], a[mi][1], a[mi][2], a[mi][3],
                        sA + swz(((rowA + (mi << 4)) << 7) + kb + kselA));
            uint32_t bf[4][4];
#pragma unroll
            for (int jj = 0; jj < 4; jj++)
                ldsm_x4(bf[jj][0], bf[jj][1], bf[jj][2], bf[jj][3],
                        sB + swz(((rowB + (jj << 4)) << 7) + kb + kselB));
#pragma unroll
            for (int mi = 0; mi < 4; mi++)
#pragma unroll
                for (int jn = 0; jn < 8; jn++)
                    mma16816(acc[mi][jn], a[mi], bf[jn >> 1][(jn & 1) << 1],
                             bf[jn >> 1][((jn & 1) << 1) + 1]);
        }
        stage++;
        if (stage == NSTAGE) stage = 0;
    }

    // epilogue: scale by sout[b][o], write fp32
    const float* svb = g_sout + (b << 9) + o0;
#pragma unroll
    for (int mi = 0; mi < 4; mi++) {
        int r0 = m0w + (mi << 4) + (lane >> 2);
        float sv0 = svb[r0];
        float sv1 = svb[r0 + 8];
        float* p0 = out + (((size_t)((b << 9) + o0 + r0)) << 12) + n0 + n0w;
        float* p1 = p0 + ((size_t)8 << 12);
#pragma unroll
        for (int jn = 0; jn < 8; jn++) {
            int c = (jn << 3) + ((lane & 3) << 1);
            float2 v0 = make_float2(acc[mi][jn][0] * sv0, acc[mi][jn][1] * sv0);
            float2 v1 = make_float2(acc[mi][jn][2] * sv1, acc[mi][jn][3] * sv1);
            *(float2*)(p0 + c) = v0;
            *(float2*)(p1 + c) = v1;
        }
    }
}

// ---------------- launch ----------------
extern "C" void kernel_launch(void* const* d_in, const int* in_sizes, int n_in,
                              void* d_out, int out_size) {
    (void)in_sizes; (void)n_in; (void)out_size;
    const float* x  = (const float*)d_in[0];
    const float* s  = (const float*)d_in[1];
    const float* w0 = (const float*)d_in[2];
    const float* b0 = (const float*)d_in[3];
    const float* a0 = (const float*)d_in[4];
    const float* w1 = (const float*)d_in[5];
    const float* b1 = (const float*)d_in[6];
    const float* a1 = (const float*)d_in[7];
    const float* sw = (const float*)d_in[8];
    const float* sb = (const float*)d_in[9];
    const float* cw = (const float*)d_in[10];
    float* out = (float*)d_out;

    cudaFuncSetAttribute(conv_kernel, cudaFuncAttributeMaxDynamicSharedMemorySize, SMEM_BYTES);

    prep_weights<<<(CO * CI) / 256, 256>>>(cw);
    linear_map<<<16, 512>>>(s, w0, b0, a0, 0);
    linear_map<<<16, 512>>>(nullptr, w1, b1, a1, 1);
    linear_map<<<16, 512>>>(nullptr, sw, sb, nullptr, 2);
    sigma_kernel<<<16, 512>>>();
    mod_pad<<<dim3(CI / 64, HPAD, BB), 256>>>(x);
    conv_kernel<<<BB * 4 * 16, 256, SMEM_BYTES>>>(out);
}

// round 4
// speedup vs baseline: 1.4018x; 1.1504x over previous
#include <cuda_runtime.h>
#include <cuda_fp16.h>
#include <cstdint>

// ---------------- problem sizes ----------------
#define BB   16
#define CI   512
#define CO   512
#define HW_  64
#define DL   512
#define HPAD 66

#define C_LIN  0.044194173824159216f   // 1/sqrt(512)
#define C_CONV 0.014731391274719739f   // 1/sqrt(512*9)

// ---------------- device scratch ----------------
__device__ __half g_wh[9 * CO * CI];                   // weights fp16, tap-major [9][CO][CI]
__device__ float  g_z0[BB * DL];
__device__ float  g_z1[BB * DL];
__device__ float  g_style[BB * CI];
__device__ float  g_sout[BB * CO];                     // c_conv * sigma_inv
__device__ __half g_xp[(size_t)BB * HPAD * HPAD * CI]; // NHWC padded modulated input

// ---------------- helpers ----------------
__device__ __forceinline__ uint32_t smem_u32(const void* p) {
    uint32_t a;
    asm("{ .reg .u64 t; cvta.to.shared.u64 t, %1; cvt.u32.u64 %0, t; }" : "=r"(a) : "l"(p));
    return a;
}

__device__ __forceinline__ uint32_t swz(uint32_t x) { return x ^ ((x >> 3) & 0x70); }

#define CP16(smem, gptr) \
    asm volatile("cp.async.cg.shared.global [%0], [%1], 16;" :: "r"(smem), "l"(gptr))
#define CP_COMMIT() asm volatile("cp.async.commit_group;" ::: "memory")
#define CP_WAIT(n)  asm volatile("cp.async.wait_group %0;" :: "n"(n) : "memory")

__device__ __forceinline__ void ldsm_x4(uint32_t& r0, uint32_t& r1, uint32_t& r2, uint32_t& r3,
                                        uint32_t addr) {
    asm volatile("ldmatrix.sync.aligned.m8n8.x4.shared.b16 {%0,%1,%2,%3}, [%4];"
                 : "=r"(r0), "=r"(r1), "=r"(r2), "=r"(r3) : "r"(addr));
}

__device__ __forceinline__ void mma16816(float* c, const uint32_t* a, uint32_t b0, uint32_t b1) {
    asm volatile(
        "mma.sync.aligned.m16n8k16.row.col.f32.f16.f16.f32 "
        "{%0,%1,%2,%3}, {%4,%5,%6,%7}, {%8,%9}, {%0,%1,%2,%3};"
        : "+f"(c[0]), "+f"(c[1]), "+f"(c[2]), "+f"(c[3])
        : "r"(a[0]), "r"(a[1]), "r"(a[2]), "r"(a[3]), "r"(b0), "r"(b1));
}

// ---------------- kernel 1: mapping layers (64 blocks x 128 thr, thread=(b,o)) -------------
__global__ void linear_map(const float* __restrict__ ext_in, const float* __restrict__ W,
                           const float* __restrict__ bias, const float* __restrict__ pa,
                           int mode) {
    __shared__ float sin_t[DL * BB];   // transposed [j][b], 32KB
    const float* in = (mode == 0) ? ext_in : (mode == 1 ? g_z0 : g_z1);
    float* out      = (mode == 0) ? g_z0   : (mode == 1 ? g_z1 : g_style);
    int tid = threadIdx.x;  // 128
    for (int idx = tid; idx < BB * DL; idx += 128) {
        int b = idx >> 9, j = idx & 511;
        sin_t[j * BB + b] = in[idx];
    }
    __syncthreads();
    int b  = tid & 15;
    int o  = blockIdx.x * 8 + (tid >> 4);
    const float4* wr = (const float4*)(W + (size_t)o * DL);
    float a0 = 0.f, a1 = 0.f, a2 = 0.f, a3 = 0.f;
#pragma unroll 8
    for (int j4 = 0; j4 < DL / 4; j4++) {
        float4 wv = __ldg(wr + j4);
        int j = j4 << 2;
        a0 = fmaf(sin_t[(j + 0) * BB + b], wv.x, a0);
        a1 = fmaf(sin_t[(j + 1) * BB + b], wv.y, a1);
        a2 = fmaf(sin_t[(j + 2) * BB + b], wv.z, a2);
        a3 = fmaf(sin_t[(j + 3) * BB + b], wv.w, a3);
    }
    float r = ((a0 + a1) + (a2 + a3)) * C_LIN + bias[o];
    if (mode < 2) r = (r >= 0.f) ? r : pa[o] * r;
    out[b * DL + o] = r;
}

// ---------------- kernel 2: sigma (wsq computed on the fly from conv_w) --------------------
__global__ void sigma_fused(const float* __restrict__ cw) {
    __shared__ float swsq[8 * CI];   // 16KB  [oi][i]
    __shared__ float st2[CI * BB];   // 32KB  [i][b]
    int tid = threadIdx.x;  // 128
    int o0 = blockIdx.x * 8;
    for (int idx = tid; idx < BB * CI; idx += 128) {
        int b = idx >> 9, i = idx & 511;
        float v = g_style[b * CI + i];
        st2[i * BB + b] = v * v;
    }
    for (int idx = tid; idx < 8 * CI; idx += 128) {
        int oi = idx >> 9, i = idx & 511;
        const float* p = cw + ((size_t)(o0 + oi) * CI + i) * 9;
        float sq = 0.f;
#pragma unroll
        for (int k = 0; k < 9; k++) sq = fmaf(p[k], p[k], sq);
        swsq[oi * CI + i] = sq;
    }
    __syncthreads();
    int b = tid & 15;
    int oi = tid >> 4;
    float a0 = 0.f, a1 = 0.f;
#pragma unroll 8
    for (int i = 0; i < CI; i += 2) {
        a0 = fmaf(st2[(i + 0) * BB + b], swsq[oi * CI + i + 0], a0);
        a1 = fmaf(st2[(i + 1) * BB + b], swsq[oi * CI + i + 1], a1);
    }
    float acc = a0 + a1;
    g_sout[b * CO + o0 + oi] = C_CONV * rsqrtf(C_CONV * C_CONV * acc + 1e-8f);
}

// ---------------- kernel 3: modulate+pad+transpose, fused with weight fp16 convert --------
#define MP_BLOCKS (8 * 66 * BB)   // 8448
__global__ void mod_pad_prep(const float* __restrict__ x, const float* __restrict__ cw) {
    int bid = blockIdx.x;
    int tid = threadIdx.x;  // 256
    if (bid >= MP_BLOCKS) {
        // weight convert: 1024 blocks x 256 threads, one (o,i) each
        int g = (bid - MP_BLOCKS) * 256 + tid;
        const float* p = cw + (size_t)g * 9;
#pragma unroll
        for (int k = 0; k < 9; k++)
            g_wh[(size_t)k * (CO * CI) + g] = __float2half(p[k]);
        return;
    }
    __shared__ float sx[64][65];
    __shared__ float sst[64];
    int i0 = (bid & 7) * 64;
    int hp = (bid >> 3) % 66;
    int b  = bid / 528;
    int h = hp - 1; h = h < 0 ? 0 : (h > 63 ? 63 : h);
    const float* xb = x + (((size_t)b * CI + i0) * 64 + h) * 64;
    for (int idx = tid; idx < 64 * 16; idx += 256) {
        int i = idx >> 4, w4 = (idx & 15) << 2;
        float4 v = *(const float4*)(xb + (size_t)i * 4096 + w4);
        sx[i][w4] = v.x; sx[i][w4 + 1] = v.y; sx[i][w4 + 2] = v.z; sx[i][w4 + 3] = v.w;
    }
    if (tid < 64) sst[tid] = g_style[b * CI + i0 + tid];
    __syncthreads();
    __half* outp = g_xp + (((size_t)b * HPAD + hp) * HPAD) * CI + i0;
    for (int idx = tid; idx < 66 * 32; idx += 256) {
        int wp = idx >> 5; int ip = (idx & 31) << 1;
        int w = wp - 1; w = w < 0 ? 0 : (w > 63 ? 63 : w);
        __half2 hv = __floats2half2_rn(sx[ip][w] * sst[ip], sx[ip + 1][w] * sst[ip + 1]);
        *(__half2*)(outp + (size_t)wp * CI + ip) = hv;
    }
}

// ---------------- kernel 4: conv, tap-slab implicit GEMM ----------------------------------
// CTA tile M=128 x N=256 (4 image rows). 24 super-chunks = 3 tap-rows(dh) x 8 ch-chunks(cc).
// Per super-chunk: B slab 4x66x64ch (33792B, serves dw=0,1,2) + A 3 taps x 16KB.
// 8 warps (2 M x 4 N), warp tile 64x64.
#define A_BYTES   49152u            // 3 x 16KB
#define B_BYTES   33792u            // 264 cells x 128B
#define STAGE_BYTES (A_BYTES + B_BYTES)   // 82944
#define SMEM_BYTES (2u * STAGE_BYTES)     // 165888
#define NSUP 24

__device__ __forceinline__ void load_super(int tid, uint32_t sbase, int stage, int s,
                                           int o0, int h0, const __half* __restrict__ xpb) {
    uint32_t sA = sbase + (uint32_t)stage * STAGE_BYTES;
    uint32_t sB = sA + A_BYTES;
    int dh = s >> 3;
    int cc = s & 7;
    // A: 3 taps (dh*3 + dw), each 128 rows x 64 ch
    {
        int idx = tid;               // 3072 pieces / 256 threads = 12
#pragma unroll
        for (int t = 0; t < 12; t++, idx += 256) {
            int dw   = idx >> 10;            // 0..2
            int row  = (idx >> 3) & 127;
            int pc   = idx & 7;
            int tap  = dh * 3 + dw;
            const __half* g = g_wh + (((size_t)(tap * 512 + o0 + row)) << 9) + (cc << 6) + (pc << 3);
            CP16(sA + (uint32_t)dw * 16384u + swz(((uint32_t)row << 7) + ((uint32_t)pc << 4)), g);
        }
    }
    // B: slab rows h0+dh .. h0+dh+3, 66 cells each, 64 ch slice cc
    {
        int h0s = h0 + dh;
        const __half* gb = xpb + (((size_t)(h0s * HPAD)) << 9) + (cc << 6);
        for (int idx = tid; idx < 2112; idx += 256) {    // 264 cells x 8 pieces
            int cell = idx >> 3;
            int pc   = idx & 7;
            CP16(sB + swz(((uint32_t)cell << 7) + ((uint32_t)pc << 4)),
                 gb + (((size_t)cell) << 9) + (pc << 3));
        }
    }
}

__global__ void __launch_bounds__(256, 1) conv_kernel(float* __restrict__ out) {
    extern __shared__ char smem[];
    const uint32_t sbase = smem_u32(smem);
    int tid  = threadIdx.x;
    int w    = tid >> 5;
    int lane = tid & 31;
    int m0w  = (w & 1) << 6;    // warp M offset 0/64
    int nrow = (w >> 1);        // warp's image-row within tile (0..3) = n0w/64

    int tile = blockIdx.x;
    int nt = tile & 15;
    int ot = (tile >> 4) & 3;
    int b  = tile >> 6;
    int o0 = ot << 7;
    int n0 = nt << 8;           // pixel offset
    int h0 = nt << 2;           // image row offset

    const __half* xpb = g_xp + (size_t)b * (HPAD * HPAD * CI);

    float acc[4][8][4];
#pragma unroll
    for (int i = 0; i < 4; i++)
#pragma unroll
        for (int jn = 0; jn < 8; jn++)
#pragma unroll
            for (int c = 0; c < 4; c++) acc[i][jn][c] = 0.f;

    // ldmatrix lane address components (same fragment mapping as validated R3 kernel)
    uint32_t rowA  = (uint32_t)(m0w + (lane & 15));
    uint32_t kselA = (uint32_t)((lane >> 4) << 4);
    uint32_t lp    = (uint32_t)((lane & 7) + ((lane & 16) >> 1));  // B lane pixel 0..15
    uint32_t kselB = (uint32_t)((lane & 8) << 1);

    // prologue
    load_super(tid, sbase, 0, 0, o0, h0, xpb);
    CP_COMMIT();

    for (int s = 0; s < NSUP; s++) {
        int st = s & 1;
        __syncthreads();                       // stage (s+1)&1 is free now
        if (s + 1 < NSUP)
            load_super(tid, sbase, (s + 1) & 1, s + 1, o0, h0, xpb);
        CP_COMMIT();
        CP_WAIT(1);                            // group s complete
        __syncthreads();                       // visibility of stage st to all warps

        uint32_t sA = sbase + (uint32_t)st * STAGE_BYTES;
        uint32_t sB = sA + A_BYTES;
#pragma unroll
        for (int dw = 0; dw < 3; dw++) {
            uint32_t sAd = sA + (uint32_t)dw * 16384u;
            // cell index base for this warp & dw: nrow*66 + lp + dw (+16*jj)
            uint32_t cell0 = (uint32_t)(nrow * 66) + lp + (uint32_t)dw;
#pragma unroll
            for (int kk = 0; kk < 4; kk++) {
                uint32_t kb = (uint32_t)(kk << 5);
                uint32_t a[4][4];
#pragma unroll
                for (int mi = 0; mi < 4; mi++)
                    ldsm_x4(a[mi][0], a[mi][1], a[mi][2], a[mi][3],
                            sAd + swz(((rowA + (mi << 4)) << 7) + kb + kselA));
                uint32_t bf[4][4];
#pragma unroll
                for (int jj = 0; jj < 4; jj++)
                    ldsm_x4(bf[jj][0], bf[jj][1], bf[jj][2], bf[jj][3],
                            sB + swz(((cell0 + (jj << 4)) << 7) + kb + kselB));
#pragma unroll
                for (int mi = 0; mi < 4; mi++)
#pragma unroll
                    for (int jn = 0; jn < 8; jn++)
                        mma16816(acc[mi][jn], a[mi], bf[jn >> 1][(jn & 1) << 1],
                                 bf[jn >> 1][((jn & 1) << 1) + 1]);
            }
        }
    }

    // epilogue: scale by sout[b][o], write fp32
    int n0w = nrow << 6;
    const float* svb = g_sout + (b << 9) + o0;
#pragma unroll
    for (int mi = 0; mi < 4; mi++) {
        int r0 = m0w + (mi << 4) + (lane >> 2);
        float sv0 = svb[r0];
        float sv1 = svb[r0 + 8];
        float* p0 = out + (((size_t)((b << 9) + o0 + r0)) << 12) + n0 + n0w;
        float* p1 = p0 + ((size_t)8 << 12);
#pragma unroll
        for (int jn = 0; jn < 8; jn++) {
            int c = (jn << 3) + ((lane & 3) << 1);
            float2 v0 = make_float2(acc[mi][jn][0] * sv0, acc[mi][jn][1] * sv0);
            float2 v1 = make_float2(acc[mi][jn][2] * sv1, acc[mi][jn][3] * sv1);
            *(float2*)(p0 + c) = v0;
            *(float2*)(p1 + c) = v1;
        }
    }
}

// ---------------- launch ----------------
extern "C" void kernel_launch(void* const* d_in, const int* in_sizes, int n_in,
                              void* d_out, int out_size) {
    (void)in_sizes; (void)n_in; (void)out_size;
    const float* x  = (const float*)d_in[0];
    const float* s  = (const float*)d_in[1];
    const float* w0 = (const float*)d_in[2];
    const float* b0 = (const float*)d_in[3];
    const float* a0 = (const float*)d_in[4];
    const float* w1 = (const float*)d_in[5];
    const float* b1 = (const float*)d_in[6];
    const float* a1 = (const float*)d_in[7];
    const float* sw = (const float*)d_in[8];
    const float* sb = (const float*)d_in[9];
    const float* cw = (const float*)d_in[10];
    float* out = (float*)d_out;

    cudaFuncSetAttribute(conv_kernel, cudaFuncAttributeMaxDynamicSharedMemorySize, SMEM_BYTES);

    linear_map<<<64, 128>>>(s, w0, b0, a0, 0);
    linear_map<<<64, 128>>>(nullptr, w1, b1, a1, 1);
    linear_map<<<64, 128>>>(nullptr, sw, sb, nullptr, 2);
    sigma_fused<<<64, 128>>>(cw);
    mod_pad_prep<<<MP_BLOCKS + 1024, 256>>>(x, cw);
    conv_kernel<<<BB * 4 * 16, 256, SMEM_BYTES>>>(out);
}

// round 5
// speedup vs baseline: 1.4116x; 1.0070x over previous
#include <cuda_runtime.h>
#include <cuda_fp16.h>
#include <cstdint>

// ---------------- problem sizes ----------------
#define BB   16
#define CI   512
#define CO   512
#define HW_  64
#define DL   512
#define HPAD 66

#define C_LIN  0.044194173824159216f   // 1/sqrt(512)
#define C_CONV 0.014731391274719739f   // 1/sqrt(512*9)

// ---------------- device scratch ----------------
__device__ __half g_wh[9 * CO * CI];                   // weights fp16, tap-major [9][CO][CI]
__device__ float  g_wsq[CO * CI];                      // sum_k conv_w^2
__device__ float  g_z0[BB * DL];
__device__ float  g_z1[BB * DL];
__device__ float  g_style[BB * CI];
__device__ float  g_sout[BB * CO];                     // c_conv * sigma_inv
__device__ __half g_xp[(size_t)BB * HPAD * HPAD * CI]; // NHWC padded modulated input

// ---------------- helpers ----------------
__device__ __forceinline__ uint32_t smem_u32(const void* p) {
    uint32_t a;
    asm("{ .reg .u64 t; cvta.to.shared.u64 t, %1; cvt.u32.u64 %0, t; }" : "=r"(a) : "l"(p));
    return a;
}

__device__ __forceinline__ uint32_t swz(uint32_t x) { return x ^ ((x >> 3) & 0x70); }

#define CP16(smem, gptr) \
    asm volatile("cp.async.cg.shared.global [%0], [%1], 16;" :: "r"(smem), "l"(gptr))
#define CP_COMMIT() asm volatile("cp.async.commit_group;" ::: "memory")
#define CP_WAIT(n)  asm volatile("cp.async.wait_group %0;" :: "n"(n) : "memory")

__device__ __forceinline__ void ldsm_x4(uint32_t& r0, uint32_t& r1, uint32_t& r2, uint32_t& r3,
                                        uint32_t addr) {
    asm volatile("ldmatrix.sync.aligned.m8n8.x4.shared.b16 {%0,%1,%2,%3}, [%4];"
                 : "=r"(r0), "=r"(r1), "=r"(r2), "=r"(r3) : "r"(addr));
}

__device__ __forceinline__ void mma16816(float* c, const uint32_t* a, uint32_t b0, uint32_t b1) {
    asm volatile(
        "mma.sync.aligned.m16n8k16.row.col.f32.f16.f16.f32 "
        "{%0,%1,%2,%3}, {%4,%5,%6,%7}, {%8,%9}, {%0,%1,%2,%3};"
        : "+f"(c[0]), "+f"(c[1]), "+f"(c[2]), "+f"(c[3])
        : "r"(a[0]), "r"(a[1]), "r"(a[2]), "r"(a[3]), "r"(b0), "r"(b1));
}

__device__ __forceinline__ void stcs4(float* p, float4 v) {
    asm volatile("st.global.cs.v4.f32 [%0], {%1,%2,%3,%4};"
                 :: "l"(p), "f"(v.x), "f"(v.y), "f"(v.z), "f"(v.w));
}

// ---------------- kernel 0: weight prep (single pass over conv_w) -------------------------
__global__ void weight_prep(const float* __restrict__ cw) {
    int g = blockIdx.x * blockDim.x + threadIdx.x;   // one (o,i) per thread
    const float* p = cw + (size_t)g * 9;
    float sq = 0.f;
#pragma unroll
    for (int k = 0; k < 9; k++) {
        float v = p[k];
        sq = fmaf(v, v, sq);
        g_wh[(size_t)k * (CO * CI) + g] = __float2half(v);
    }
    g_wsq[g] = sq;
}

// ---------------- kernel 1: mapping layers (64 blocks x 128 thr, thread=(b,o)) -------------
__global__ void linear_map(const float* __restrict__ ext_in, const float* __restrict__ W,
                           const float* __restrict__ bias, const float* __restrict__ pa,
                           int mode) {
    __shared__ float sin_t[DL * BB];   // transposed [j][b], 32KB
    const float* in = (mode == 0) ? ext_in : (mode == 1 ? g_z0 : g_z1);
    float* out      = (mode == 0) ? g_z0   : (mode == 1 ? g_z1 : g_style);
    int tid = threadIdx.x;  // 128
    for (int idx = tid; idx < BB * DL; idx += 128) {
        int b = idx >> 9, j = idx & 511;
        sin_t[j * BB + b] = in[idx];
    }
    __syncthreads();
    int b  = tid & 15;
    int o  = blockIdx.x * 8 + (tid >> 4);
    const float4* wr = (const float4*)(W + (size_t)o * DL);
    float a0 = 0.f, a1 = 0.f, a2 = 0.f, a3 = 0.f;
#pragma unroll 8
    for (int j4 = 0; j4 < DL / 4; j4++) {
        float4 wv = __ldg(wr + j4);
        int j = j4 << 2;
        a0 = fmaf(sin_t[(j + 0) * BB + b], wv.x, a0);
        a1 = fmaf(sin_t[(j + 1) * BB + b], wv.y, a1);
        a2 = fmaf(sin_t[(j + 2) * BB + b], wv.z, a2);
        a3 = fmaf(sin_t[(j + 3) * BB + b], wv.w, a3);
    }
    float r = ((a0 + a1) + (a2 + a3)) * C_LIN + bias[o];
    if (mode < 2) r = (r >= 0.f) ? r : pa[o] * r;
    out[b * DL + o] = r;
}

// ---------------- kernel 2: sigma from precomputed wsq ------------------------------------
__global__ void sigma_kernel() {
    __shared__ float st2[CI * BB];   // 32KB [i][b]
    int tid = threadIdx.x;  // 128
    int o0 = blockIdx.x * 8;
    for (int idx = tid; idx < BB * CI; idx += 128) {
        int b = idx >> 9, i = idx & 511;
        float v = g_style[b * CI + i];
        st2[i * BB + b] = v * v;
    }
    __syncthreads();
    int b  = tid & 15;
    int oi = tid >> 4;
    const float4* wr = (const float4*)(g_wsq + (size_t)(o0 + oi) * CI);
    float a0 = 0.f, a1 = 0.f, a2 = 0.f, a3 = 0.f;
#pragma unroll 8
    for (int j4 = 0; j4 < CI / 4; j4++) {
        float4 wv = __ldg(wr + j4);
        int i = j4 << 2;
        a0 = fmaf(st2[(i + 0) * BB + b], wv.x, a0);
        a1 = fmaf(st2[(i + 1) * BB + b], wv.y, a1);
        a2 = fmaf(st2[(i + 2) * BB + b], wv.z, a2);
        a3 = fmaf(st2[(i + 3) * BB + b], wv.w, a3);
    }
    float acc = (a0 + a1) + (a2 + a3);
    g_sout[b * CO + o0 + oi] = C_CONV * rsqrtf(C_CONV * C_CONV * acc + 1e-8f);
}

// ---------------- kernel 3: modulate + edge-pad + NCHW->NHWC fp16 -------------------------
__global__ void mod_pad(const float* __restrict__ x) {
    __shared__ float sx[64][65];
    __shared__ float sst[64];
    int bid = blockIdx.x;
    int tid = threadIdx.x;  // 256
    int i0 = (bid & 7) * 64;
    int hp = (bid >> 3) % 66;
    int b  = bid / 528;
    int h = hp - 1; h = h < 0 ? 0 : (h > 63 ? 63 : h);
    const float* xb = x + (((size_t)b * CI + i0) * 64 + h) * 64;
    for (int idx = tid; idx < 64 * 16; idx += 256) {
        int i = idx >> 4, w4 = (idx & 15) << 2;
        float4 v = *(const float4*)(xb + (size_t)i * 4096 + w4);
        sx[i][w4] = v.x; sx[i][w4 + 1] = v.y; sx[i][w4 + 2] = v.z; sx[i][w4 + 3] = v.w;
    }
    if (tid < 64) sst[tid] = g_style[b * CI + i0 + tid];
    __syncthreads();
    __half* outp = g_xp + (((size_t)b * HPAD + hp) * HPAD) * CI + i0;
    for (int idx = tid; idx < 66 * 32; idx += 256) {
        int wp = idx >> 5; int ip = (idx & 31) << 1;
        int w = wp - 1; w = w < 0 ? 0 : (w > 63 ? 63 : w);
        __half2 hv = __floats2half2_rn(sx[ip][w] * sst[ip], sx[ip + 1][w] * sst[ip + 1]);
        *(__half2*)(outp + (size_t)wp * CI + ip) = hv;
    }
}

// ---------------- kernel 4: conv, tap-slab implicit GEMM ----------------------------------
#define A_BYTES   49152u            // 3 x 16KB
#define B_BYTES   33792u            // 264 cells x 128B
#define STAGE_BYTES (A_BYTES + B_BYTES)   // 82944
#define SMEM_BYTES (2u * STAGE_BYTES)     // 165888
#define NSUP 24

__device__ __forceinline__ void load_super(int tid, uint32_t sbase, int stage, int s,
                                           int o0, int h0, const __half* __restrict__ xpb) {
    uint32_t sA = sbase + (uint32_t)stage * STAGE_BYTES;
    uint32_t sB = sA + A_BYTES;
    int dh = s >> 3;
    int cc = s & 7;
    {
        int idx = tid;               // 3072 pieces / 256 threads = 12
#pragma unroll
        for (int t = 0; t < 12; t++, idx += 256) {
            int dw   = idx >> 10;
            int row  = (idx >> 3) & 127;
            int pc   = idx & 7;
            int tap  = dh * 3 + dw;
            const __half* g = g_wh + (((size_t)(tap * 512 + o0 + row)) << 9) + (cc << 6) + (pc << 3);
            CP16(sA + (uint32_t)dw * 16384u + swz(((uint32_t)row << 7) + ((uint32_t)pc << 4)), g);
        }
    }
    {
        int h0s = h0 + dh;
        const __half* gb = xpb + (((size_t)(h0s * HPAD)) << 9) + (cc << 6);
        for (int idx = tid; idx < 2112; idx += 256) {
            int cell = idx >> 3;
            int pc   = idx & 7;
            CP16(sB + swz(((uint32_t)cell << 7) + ((uint32_t)pc << 4)),
                 gb + (((size_t)cell) << 9) + (pc << 3));
        }
    }
}

__global__ void __launch_bounds__(256, 1) conv_kernel(float* __restrict__ out) {
    extern __shared__ char smem[];
    const uint32_t sbase = smem_u32(smem);
    int tid  = threadIdx.x;
    int w    = tid >> 5;
    int lane = tid & 31;
    int m0w  = (w & 1) << 6;
    int nrow = (w >> 1);

    int tile = blockIdx.x;
    int nt = tile & 15;
    int ot = (tile >> 4) & 3;
    int b  = tile >> 6;
    int o0 = ot << 7;
    int n0 = nt << 8;
    int h0 = nt << 2;

    const __half* xpb = g_xp + (size_t)b * (HPAD * HPAD * CI);

    float acc[4][8][4];
#pragma unroll
    for (int i = 0; i < 4; i++)
#pragma unroll
        for (int jn = 0; jn < 8; jn++)
#pragma unroll
            for (int c = 0; c < 4; c++) acc[i][jn][c] = 0.f;

    uint32_t rowA  = (uint32_t)(m0w + (lane & 15));
    uint32_t kselA = (uint32_t)((lane >> 4) << 4);
    uint32_t lp    = (uint32_t)((lane & 7) + ((lane & 16) >> 1));
    uint32_t kselB = (uint32_t)((lane & 8) << 1);

    load_super(tid, sbase, 0, 0, o0, h0, xpb);
    CP_COMMIT();

    for (int s = 0; s < NSUP; s++) {
        int st = s & 1;
        __syncthreads();
        if (s + 1 < NSUP)
            load_super(tid, sbase, (s + 1) & 1, s + 1, o0, h0, xpb);
        CP_COMMIT();
        CP_WAIT(1);
        __syncthreads();

        uint32_t sA = sbase + (uint32_t)st * STAGE_BYTES;
        uint32_t sB = sA + A_BYTES;
#pragma unroll
        for (int dw = 0; dw < 3; dw++) {
            uint32_t sAd = sA + (uint32_t)dw * 16384u;
            uint32_t cell0 = (uint32_t)(nrow * 66) + lp + (uint32_t)dw;
#pragma unroll
            for (int kk = 0; kk < 4; kk++) {
                uint32_t kb = (uint32_t)(kk << 5);
                uint32_t a[4][4];
#pragma unroll
                for (int mi = 0; mi < 4; mi++)
                    ldsm_x4(a[mi][0], a[mi][1], a[mi][2], a[mi][3],
                            sAd + swz(((rowA + (mi << 4)) << 7) + kb + kselA));
                uint32_t bf[4][4];
#pragma unroll
                for (int jj = 0; jj < 4; jj++)
                    ldsm_x4(bf[jj][0], bf[jj][1], bf[jj][2], bf[jj][3],
                            sB + swz(((cell0 + (jj << 4)) << 7) + kb + kselB));
#pragma unroll
                for (int mi = 0; mi < 4; mi++)
#pragma unroll
                    for (int jn = 0; jn < 8; jn++)
                        mma16816(acc[mi][jn], a[mi], bf[jn >> 1][(jn & 1) << 1],
                                 bf[jn >> 1][((jn & 1) << 1) + 1]);
            }
        }
    }

    // epilogue: scale by sout[b][o], streaming fp32 stores (don't pollute L2)
    int n0w = nrow << 6;
    const float* svb = g_sout + (b << 9) + o0;
#pragma unroll
    for (int mi = 0; mi < 4; mi++) {
        int r0 = m0w + (mi << 4) + (lane >> 2);
        float sv0 = svb[r0];
        float sv1 = svb[r0 + 8];
        float* p0 = out + (((size_t)((b << 9) + o0 + r0)) << 12) + n0 + n0w;
        float* p1 = p0 + ((size_t)8 << 12);
#pragma unroll
        for (int jp = 0; jp < 4; jp++) {     // pair adjacent jn (n8 halves) -> 128b stores
            int jn = jp << 1;
            int c = (jp << 4) + ((lane & 3) << 1);
            // acc[mi][jn] covers n-cols c..c+1, acc[mi][jn+1] covers c+8..c+9 (same jj tile)
            float2 v00 = make_float2(acc[mi][jn][0] * sv0, acc[mi][jn][1] * sv0);
            float2 v01 = make_float2(acc[mi][jn + 1][0] * sv0, acc[mi][jn + 1][1] * sv0);
            float2 v10 = make_float2(acc[mi][jn][2] * sv1, acc[mi][jn][3] * sv1);
            float2 v11 = make_float2(acc[mi][jn + 1][2] * sv1, acc[mi][jn + 1][3] * sv1);
            asm volatile("st.global.cs.v2.f32 [%0], {%1,%2};" :: "l"(p0 + c),     "f"(v00.x), "f"(v00.y));
            asm volatile("st.global.cs.v2.f32 [%0], {%1,%2};" :: "l"(p0 + c + 8), "f"(v01.x), "f"(v01.y));
            asm volatile("st.global.cs.v2.f32 [%0], {%1,%2};" :: "l"(p1 + c),     "f"(v10.x), "f"(v10.y));
            asm volatile("st.global.cs.v2.f32 [%0], {%1,%2};" :: "l"(p1 + c + 8), "f"(v11.x), "f"(v11.y));
        }
    }
}

// ---------------- launch ----------------
extern "C" void kernel_launch(void* const* d_in, const int* in_sizes, int n_in,
                              void* d_out, int out_size) {
    (void)in_sizes; (void)n_in; (void)out_size;
    const float* x  = (const float*)d_in[0];
    const float* s  = (const float*)d_in[1];
    const float* w0 = (const float*)d_in[2];
    const float* b0 = (const float*)d_in[3];
    const float* a0 = (const float*)d_in[4];
    const float* w1 = (const float*)d_in[5];
    const float* b1 = (const float*)d_in[6];
    const float* a1 = (const float*)d_in[7];
    const float* sw = (const float*)d_in[8];
    const float* sb = (const float*)d_in[9];
    const float* cw = (const float*)d_in[10];
    float* out = (float*)d_out;

    cudaFuncSetAttribute(conv_kernel, cudaFuncAttributeMaxDynamicSharedMemorySize, SMEM_BYTES);

    weight_prep<<<(CO * CI) / 256, 256>>>(cw);
    linear_map<<<64, 128>>>(s, w0, b0, a0, 0);
    linear_map<<<64, 128>>>(nullptr, w1, b1, a1, 1);
    linear_map<<<64, 128>>>(nullptr, sw, sb, nullptr, 2);
    sigma_kernel<<<64, 128>>>();
    mod_pad<<<8 * 66 * BB, 256>>>(x);
    conv_kernel<<<BB * 4 * 16, 256, SMEM_BYTES>>>(out);
}

// round 6
// speedup vs baseline: 1.4286x; 1.0120x over previous
#include <cuda_runtime.h>
#include <cuda_fp16.h>
#include <cstdint>

// ---------------- problem sizes ----------------
#define BB   16
#define CI   512
#define CO   512
#define HW_  64
#define DL   512
#define HPAD 66

#define C_LIN  0.044194173824159216f   // 1/sqrt(512)
#define C_CONV 0.014731391274719739f   // 1/sqrt(512*9)

// ---------------- device scratch ----------------
__device__ __half g_wh[9 * CO * CI];                   // weights fp16, tap-major [9][CO][CI]
__device__ float  g_wsq[CO * CI];                      // sum_k conv_w^2
__device__ float  g_z0[BB * DL];
__device__ float  g_z1[BB * DL];
__device__ float  g_style[BB * CI];
__device__ float  g_sout[BB * CO];                     // c_conv * sigma_inv
__device__ __half g_xp[(size_t)BB * HPAD * HPAD * CI]; // NHWC padded modulated input

// ---------------- helpers ----------------
__device__ __forceinline__ uint32_t smem_u32(const void* p) {
    uint32_t a;
    asm("{ .reg .u64 t; cvta.to.shared.u64 t, %1; cvt.u32.u64 %0, t; }" : "=r"(a) : "l"(p));
    return a;
}

__device__ __forceinline__ uint32_t swz(uint32_t x) { return x ^ ((x >> 3) & 0x70); }

#define CP16(smem, gptr) \
    asm volatile("cp.async.cg.shared.global [%0], [%1], 16;" :: "r"(smem), "l"(gptr))
#define CP_COMMIT() asm volatile("cp.async.commit_group;" ::: "memory")
#define CP_WAIT(n)  asm volatile("cp.async.wait_group %0;" :: "n"(n) : "memory")

__device__ __forceinline__ void ldsm_x4(uint32_t& r0, uint32_t& r1, uint32_t& r2, uint32_t& r3,
                                        uint32_t addr) {
    asm volatile("ldmatrix.sync.aligned.m8n8.x4.shared.b16 {%0,%1,%2,%3}, [%4];"
                 : "=r"(r0), "=r"(r1), "=r"(r2), "=r"(r3) : "r"(addr));
}

__device__ __forceinline__ void mma16816(float* c, const uint32_t* a, uint32_t b0, uint32_t b1) {
    asm volatile(
        "mma.sync.aligned.m16n8k16.row.col.f32.f16.f16.f32 "
        "{%0,%1,%2,%3}, {%4,%5,%6,%7}, {%8,%9}, {%0,%1,%2,%3};"
        : "+f"(c[0]), "+f"(c[1]), "+f"(c[2]), "+f"(c[3])
        : "r"(a[0]), "r"(a[1]), "r"(a[2]), "r"(a[3]), "r"(b0), "r"(b1));
}

// ---------------- kernel A: linear layer (32 blocks) + optional weight prep (1024 blocks) --
// block = 256 threads. Linear part: 16 o x 16 b per block.
__global__ void lin_wp(const float* __restrict__ ext_in, const float* __restrict__ W,
                       const float* __restrict__ bias, const float* __restrict__ pa,
                       const float* __restrict__ cw, int mode) {
    int bid = blockIdx.x;
    int tid = threadIdx.x;  // 256
    if (bid >= 32) {
        // weight prep: one (o,i) per thread, single pass over conv_w
        int g = (bid - 32) * 256 + tid;
        const float* p = cw + (size_t)g * 9;
        float sq = 0.f;
#pragma unroll
        for (int k = 0; k < 9; k++) {
            float v = p[k];
            sq = fmaf(v, v, sq);
            g_wh[(size_t)k * (CO * CI) + g] = __float2half(v);
        }
        g_wsq[g] = sq;
        return;
    }
    __shared__ float sin_t[DL * BB];   // transposed [j][b], 32KB
    const float* in = (mode == 0) ? ext_in : (mode == 1 ? g_z0 : g_z1);
    float* out      = (mode == 0) ? g_z0   : (mode == 1 ? g_z1 : g_style);
    // float4 staging: 2048 float4 / 256 threads = 8 each, all in flight
#pragma unroll
    for (int t = 0; t < 8; t++) {
        int idx = tid + t * 256;
        int b = idx & 15, j4 = idx >> 4;
        float4 v = *(const float4*)(in + b * DL + (j4 << 2));
        int j = j4 << 2;
        sin_t[(j + 0) * BB + b] = v.x;
        sin_t[(j + 1) * BB + b] = v.y;
        sin_t[(j + 2) * BB + b] = v.z;
        sin_t[(j + 3) * BB + b] = v.w;
    }
    __syncthreads();
    int b = tid & 15;
    int o = bid * 16 + (tid >> 4);
    const float4* wr = (const float4*)(W + (size_t)o * DL);
    float a0 = 0.f, a1 = 0.f, a2 = 0.f, a3 = 0.f;
#pragma unroll 16
    for (int j4 = 0; j4 < DL / 4; j4++) {
        float4 wv = __ldg(wr + j4);
        int j = j4 << 2;
        a0 = fmaf(sin_t[(j + 0) * BB + b], wv.x, a0);
        a1 = fmaf(sin_t[(j + 1) * BB + b], wv.y, a1);
        a2 = fmaf(sin_t[(j + 2) * BB + b], wv.z, a2);
        a3 = fmaf(sin_t[(j + 3) * BB + b], wv.w, a3);
    }
    float r = ((a0 + a1) + (a2 + a3)) * C_LIN + bias[o];
    if (mode < 2) r = (r >= 0.f) ? r : pa[o] * r;
    out[b * DL + o] = r;
}

// ---------------- kernel B: mod_pad (8448 blocks) + sigma (32 blocks) ----------------------
#define MP_BLOCKS (8 * 66 * BB)   // 8448
__global__ void modpad_sigma(const float* __restrict__ x) {
    __shared__ float smem_u[DL * BB];   // 32KB union
    int bid = blockIdx.x;
    int tid = threadIdx.x;  // 256
    if (bid >= MP_BLOCKS) {
        // ---- sigma: sout[b][o] = c_conv * rsqrt(c^2 * sum_i wsq[o,i]*style[b,i]^2 + eps)
        float* st2 = smem_u;   // [i][b]
#pragma unroll
        for (int t = 0; t < 8; t++) {
            int idx = tid + t * 256;
            int b = idx & 15, j4 = idx >> 4;
            float4 v = *(const float4*)(g_style + b * CI + (j4 << 2));
            int i = j4 << 2;
            st2[(i + 0) * BB + b] = v.x * v.x;
            st2[(i + 1) * BB + b] = v.y * v.y;
            st2[(i + 2) * BB + b] = v.z * v.z;
            st2[(i + 3) * BB + b] = v.w * v.w;
        }
        __syncthreads();
        int b  = tid & 15;
        int o  = (bid - MP_BLOCKS) * 16 + (tid >> 4);
        const float4* wr = (const float4*)(g_wsq + (size_t)o * CI);
        float a0 = 0.f, a1 = 0.f, a2 = 0.f, a3 = 0.f;
#pragma unroll 16
        for (int j4 = 0; j4 < CI / 4; j4++) {
            float4 wv = __ldg(wr + j4);
            int i = j4 << 2;
            a0 = fmaf(st2[(i + 0) * BB + b], wv.x, a0);
            a1 = fmaf(st2[(i + 1) * BB + b], wv.y, a1);
            a2 = fmaf(st2[(i + 2) * BB + b], wv.z, a2);
            a3 = fmaf(st2[(i + 3) * BB + b], wv.w, a3);
        }
        float acc = (a0 + a1) + (a2 + a3);
        g_sout[b * CO + o] = C_CONV * rsqrtf(C_CONV * C_CONV * acc + 1e-8f);
        return;
    }
    // ---- mod_pad: modulate + edge-pad + NCHW->NHWC fp16
    float (*sx)[65] = (float(*)[65])smem_u;
    float* sst = smem_u + 64 * 65;
    int i0 = (bid & 7) * 64;
    int hp = (bid >> 3) % 66;
    int b  = bid / 528;
    int h = hp - 1; h = h < 0 ? 0 : (h > 63 ? 63 : h);
    const float* xb = x + (((size_t)b * CI + i0) * 64 + h) * 64;
    for (int idx = tid; idx < 64 * 16; idx += 256) {
        int i = idx >> 4, w4 = (idx & 15) << 2;
        float4 v = *(const float4*)(xb + (size_t)i * 4096 + w4);
        sx[i][w4] = v.x; sx[i][w4 + 1] = v.y; sx[i][w4 + 2] = v.z; sx[i][w4 + 3] = v.w;
    }
    if (tid < 64) sst[tid] = g_style[b * CI + i0 + tid];
    __syncthreads();
    __half* outp = g_xp + (((size_t)b * HPAD + hp) * HPAD) * CI + i0;
    for (int idx = tid; idx < 66 * 32; idx += 256) {
        int wp = idx >> 5; int ip = (idx & 31) << 1;
        int w = wp - 1; w = w < 0 ? 0 : (w > 63 ? 63 : w);
        __half2 hv = __floats2half2_rn(sx[ip][w] * sst[ip], sx[ip + 1][w] * sst[ip + 1]);
        *(__half2*)(outp + (size_t)wp * CI + ip) = hv;
    }
}

// ---------------- kernel C: conv, tap-slab implicit GEMM (unchanged from R5) ---------------
#define A_BYTES   49152u            // 3 x 16KB
#define B_BYTES   33792u            // 264 cells x 128B
#define STAGE_BYTES (A_BYTES + B_BYTES)   // 82944
#define SMEM_BYTES (2u * STAGE_BYTES)     // 165888
#define NSUP 24

__device__ __forceinline__ void load_super(int tid, uint32_t sbase, int stage, int s,
                                           int o0, int h0, const __half* __restrict__ xpb) {
    uint32_t sA = sbase + (uint32_t)stage * STAGE_BYTES;
    uint32_t sB = sA + A_BYTES;
    int dh = s >> 3;
    int cc = s & 7;
    {
        int idx = tid;               // 3072 pieces / 256 threads = 12
#pragma unroll
        for (int t = 0; t < 12; t++, idx += 256) {
            int dw   = idx >> 10;
            int row  = (idx >> 3) & 127;
            int pc   = idx & 7;
            int tap  = dh * 3 + dw;
            const __half* g = g_wh + (((size_t)(tap * 512 + o0 + row)) << 9) + (cc << 6) + (pc << 3);
            CP16(sA + (uint32_t)dw * 16384u + swz(((uint32_t)row << 7) + ((uint32_t)pc << 4)), g);
        }
    }
    {
        int h0s = h0 + dh;
        const __half* gb = xpb + (((size_t)(h0s * HPAD)) << 9) + (cc << 6);
        for (int idx = tid; idx < 2112; idx += 256) {
            int cell = idx >> 3;
            int pc   = idx & 7;
            CP16(sB + swz(((uint32_t)cell << 7) + ((uint32_t)pc << 4)),
                 gb + (((size_t)cell) << 9) + (pc << 3));
        }
    }
}

__global__ void __launch_bounds__(256, 1) conv_kernel(float* __restrict__ out) {
    extern __shared__ char smem[];
    const uint32_t sbase = smem_u32(smem);
    int tid  = threadIdx.x;
    int w    = tid >> 5;
    int lane = tid & 31;
    int m0w  = (w & 1) << 6;
    int nrow = (w >> 1);

    int tile = blockIdx.x;
    int nt = tile & 15;
    int ot = (tile >> 4) & 3;
    int b  = tile >> 6;
    int o0 = ot << 7;
    int n0 = nt << 8;
    int h0 = nt << 2;

    const __half* xpb = g_xp + (size_t)b * (HPAD * HPAD * CI);

    float acc[4][8][4];
#pragma unroll
    for (int i = 0; i < 4; i++)
#pragma unroll
        for (int jn = 0; jn < 8; jn++)
#pragma unroll
            for (int c = 0; c < 4; c++) acc[i][jn][c] = 0.f;

    uint32_t rowA  = (uint32_t)(m0w + (lane & 15));
    uint32_t kselA = (uint32_t)((lane >> 4) << 4);
    uint32_t lp    = (uint32_t)((lane & 7) + ((lane & 16) >> 1));
    uint32_t kselB = (uint32_t)((lane & 8) << 1);

    load_super(tid, sbase, 0, 0, o0, h0, xpb);
    CP_COMMIT();

    for (int s = 0; s < NSUP; s++) {
        int st = s & 1;
        __syncthreads();
        if (s + 1 < NSUP)
            load_super(tid, sbase, (s + 1) & 1, s + 1, o0, h0, xpb);
        CP_COMMIT();
        CP_WAIT(1);
        __syncthreads();

        uint32_t sA = sbase + (uint32_t)st * STAGE_BYTES;
        uint32_t sB = sA + A_BYTES;
#pragma unroll
        for (int dw = 0; dw < 3; dw++) {
            uint32_t sAd = sA + (uint32_t)dw * 16384u;
            uint32_t cell0 = (uint32_t)(nrow * 66) + lp + (uint32_t)dw;
#pragma unroll
            for (int kk = 0; kk < 4; kk++) {
                uint32_t kb = (uint32_t)(kk << 5);
                uint32_t a[4][4];
#pragma unroll
                for (int mi = 0; mi < 4; mi++)
                    ldsm_x4(a[mi][0], a[mi][1], a[mi][2], a[mi][3],
                            sAd + swz(((rowA + (mi << 4)) << 7) + kb + kselA));
                uint32_t bf[4][4];
#pragma unroll
                for (int jj = 0; jj < 4; jj++)
                    ldsm_x4(bf[jj][0], bf[jj][1], bf[jj][2], bf[jj][3],
                            sB + swz(((cell0 + (jj << 4)) << 7) + kb + kselB));
#pragma unroll
                for (int mi = 0; mi < 4; mi++)
#pragma unroll
                    for (int jn = 0; jn < 8; jn++)
                        mma16816(acc[mi][jn], a[mi], bf[jn >> 1][(jn & 1) << 1],
                                 bf[jn >> 1][((jn & 1) << 1) + 1]);
            }
        }
    }

    // epilogue: scale by sout[b][o], streaming fp32 stores
    int n0w = nrow << 6;
    const float* svb = g_sout + (b << 9) + o0;
#pragma unroll
    for (int mi = 0; mi < 4; mi++) {
        int r0 = m0w + (mi << 4) + (lane >> 2);
        float sv0 = svb[r0];
        float sv1 = svb[r0 + 8];
        float* p0 = out + (((size_t)((b << 9) + o0 + r0)) << 12) + n0 + n0w;
        float* p1 = p0 + ((size_t)8 << 12);
#pragma unroll
        for (int jp = 0; jp < 4; jp++) {
            int jn = jp << 1;
            int c = (jp << 4) + ((lane & 3) << 1);
            float2 v00 = make_float2(acc[mi][jn][0] * sv0, acc[mi][jn][1] * sv0);
            float2 v01 = make_float2(acc[mi][jn + 1][0] * sv0, acc[mi][jn + 1][1] * sv0);
            float2 v10 = make_float2(acc[mi][jn][2] * sv1, acc[mi][jn][3] * sv1);
            float2 v11 = make_float2(acc[mi][jn + 1][2] * sv1, acc[mi][jn + 1][3] * sv1);
            asm volatile("st.global.cs.v2.f32 [%0], {%1,%2};" :: "l"(p0 + c),     "f"(v00.x), "f"(v00.y));
            asm volatile("st.global.cs.v2.f32 [%0], {%1,%2};" :: "l"(p0 + c + 8), "f"(v01.x), "f"(v01.y));
            asm volatile("st.global.cs.v2.f32 [%0], {%1,%2};" :: "l"(p1 + c),     "f"(v10.x), "f"(v10.y));
            asm volatile("st.global.cs.v2.f32 [%0], {%1,%2};" :: "l"(p1 + c + 8), "f"(v11.x), "f"(v11.y));
        }
    }
}

// ---------------- launch ----------------
extern "C" void kernel_launch(void* const* d_in, const int* in_sizes, int n_in,
                              void* d_out, int out_size) {
    (void)in_sizes; (void)n_in; (void)out_size;
    const float* x  = (const float*)d_in[0];
    const float* s  = (const float*)d_in[1];
    const float* w0 = (const float*)d_in[2];
    const float* b0 = (const float*)d_in[3];
    const float* a0 = (const float*)d_in[4];
    const float* w1 = (const float*)d_in[5];
    const float* b1 = (const float*)d_in[6];
    const float* a1 = (const float*)d_in[7];
    const float* sw = (const float*)d_in[8];
    const float* sb = (const float*)d_in[9];
    const float* cw = (const float*)d_in[10];
    float* out = (float*)d_out;

    cudaFuncSetAttribute(conv_kernel, cudaFuncAttributeMaxDynamicSharedMemorySize, SMEM_BYTES);

    lin_wp<<<32 + 1024, 256>>>(s, w0, b0, a0, cw, 0);       // layer 0 + weight prep
    lin_wp<<<32, 256>>>(nullptr, w1, b1, a1, nullptr, 1);   // layer 1
    lin_wp<<<32, 256>>>(nullptr, sw, sb, nullptr, nullptr, 2); // style layer
    modpad_sigma<<<MP_BLOCKS + 32, 256>>>(x);               // modulate/pad + sigma
    conv_kernel<<<BB * 4 * 16, 256, SMEM_BYTES>>>(out);
}